// round 1
// baseline (speedup 1.0000x reference)
#include <cuda_runtime.h>
#include <math.h>

#define DIM   1024
#define NCAND 16384
#define SSZ   512
#define MSZ   4096
#define LSZ   8192
#define KPROM 128

// ---------------- device scratch (no allocations allowed) ----------------
__device__ float g_norms[NCAND];
__device__ int   g_topidx[KPROM];
__device__ float g_part[64 * DIM];
__device__ float g_lmean[DIM];
__device__ float g_q[DIM];
__device__ float g_u[DIM];
__device__ float g_logits[SSZ];
__device__ int   g_best_s;
__device__ float g_cand[DIM];
__device__ float g_cnsq;
__device__ float g_mdot[MSZ];
__device__ float g_mnsq[MSZ];
__device__ float g_minv[MSZ];
__device__ int   g_msi;
__device__ float g_simcand;
__device__ unsigned long long g_pairmax;
__device__ float g_mumean, g_lumean;
__device__ int   g_li, g_lj, g_isfull, g_mi;

// ---------------- helpers ----------------
__device__ __forceinline__ float blockReduceSum(float v) {
    __shared__ float sh[32];
    int lane = threadIdx.x & 31, wid = threadIdx.x >> 5;
    __syncthreads();
#pragma unroll
    for (int o = 16; o; o >>= 1) v += __shfl_down_sync(0xFFFFFFFFu, v, o);
    if (lane == 0) sh[wid] = v;
    __syncthreads();
    int nw = (blockDim.x + 31) >> 5;
    v = (threadIdx.x < nw) ? sh[threadIdx.x] : 0.f;
    if (wid == 0) {
#pragma unroll
        for (int o = 16; o; o >>= 1) v += __shfl_down_sync(0xFFFFFFFFu, v, o);
    }
    return v;  // valid in tid 0
}

// argmax/argmin with first-occurrence tie-break (matches jnp.argmax/argmin)
__device__ __forceinline__ void blockArgBest(float v, int idx, int maxMode,
                                             float* outv, int* outi) {
    __shared__ float sv[256];
    __shared__ int   si[256];
    __syncthreads();
    sv[threadIdx.x] = v; si[threadIdx.x] = idx;
    __syncthreads();
    for (int s = blockDim.x >> 1; s; s >>= 1) {
        if ((int)threadIdx.x < s) {
            float v2 = sv[threadIdx.x + s]; int i2 = si[threadIdx.x + s];
            bool better = maxMode
                ? (v2 > sv[threadIdx.x] || (v2 == sv[threadIdx.x] && i2 < si[threadIdx.x]))
                : (v2 < sv[threadIdx.x] || (v2 == sv[threadIdx.x] && i2 < si[threadIdx.x]));
            if (better) { sv[threadIdx.x] = v2; si[threadIdx.x] = i2; }
        }
        __syncthreads();
    }
    if (threadIdx.x == 0) { if (outv) *outv = sv[0]; *outi = si[0]; }
    __syncthreads();
}

__device__ __forceinline__ unsigned ordf(float f) {
    unsigned u = __float_as_uint(f);
    return (u & 0x80000000u) ? ~u : (u | 0x80000000u);
}
__device__ __forceinline__ float iordf(unsigned u) {
    unsigned b = (u & 0x80000000u) ? (u & 0x7FFFFFFFu) : ~u;
    return __uint_as_float(b);
}

// ---------------- kernels ----------------
__global__ void k_init() { if (threadIdx.x == 0) g_pairmax = 0ULL; }

// squared norms of candidate rows (16384 x 1024)
__global__ void k_rownorms(const float* __restrict__ cand) {
    int row = blockIdx.x, t = threadIdx.x;  // 128 threads
    const float4* p = (const float4*)(cand + (size_t)row * DIM);
    float4 a = p[t], b = p[t + 128];
    float s = a.x*a.x + a.y*a.y + a.z*a.z + a.w*a.w
            + b.x*b.x + b.y*b.y + b.z*b.z + b.w*b.w;
    float tot = blockReduceSum(s);
    if (t == 0) g_norms[row] = tot;  // normsq: monotone w.r.t. norm for top-k
}

// iterative top-128 (destructive masking); single block, 256 threads
__global__ void k_topk() {
    int tid = threadIdx.x;
    __shared__ float sv[256];
    __shared__ int   si[256];
    for (int it = 0; it < KPROM; ++it) {
        float bv = -1.f; int bi = 0;
        for (int i = tid; i < NCAND; i += 256) {
            float v = g_norms[i];
            if (v > bv) { bv = v; bi = i; }
        }
        sv[tid] = bv; si[tid] = bi;
        __syncthreads();
        for (int s = 128; s; s >>= 1) {
            if (tid < s) {
                if (sv[tid + s] > sv[tid] ||
                    (sv[tid + s] == sv[tid] && si[tid + s] < si[tid])) {
                    sv[tid] = sv[tid + s]; si[tid] = si[tid + s];
                }
            }
            __syncthreads();
        }
        if (tid == 0) { g_topidx[it] = si[0]; g_norms[si[0]] = -1.f; }
        __syncthreads();
    }
}

// build s_mem output: ring-buffer scatter of top-K candidates
__global__ void k_build_s(const float* __restrict__ cand,
                          const float* __restrict__ s_in,
                          const int* __restrict__ sptr,
                          float* __restrict__ out_s) {
    int r = blockIdx.x, t = threadIdx.x;  // 512 blocks x 256 threads
    int sp = *sptr;
    int d = ((r - sp) % SSZ + SSZ) % SSZ;
    const float* src = (d < KPROM) ? (cand + (size_t)g_topidx[d] * DIM)
                                   : (s_in + (size_t)r * DIM);
    ((float4*)(out_s + (size_t)r * DIM))[t] = ((const float4*)src)[t];
}

// l_memory column partial sums (deterministic, no float atomics)
__global__ void k_lpart(const float* __restrict__ l) {
    int b = blockIdx.x, t = threadIdx.x;  // 64 blocks x 256 threads
    float acc[4] = {0.f, 0.f, 0.f, 0.f};
    int r0 = b * 128;
    for (int r = 0; r < 128; ++r) {
        const float* row = l + (size_t)(r0 + r) * DIM;
#pragma unroll
        for (int k = 0; k < 4; ++k) acc[k] += row[t + k * 256];
    }
#pragma unroll
    for (int k = 0; k < 4; ++k) g_part[b * DIM + t + k * 256] = acc[k];
}
__global__ void k_lsum() {
    int t = threadIdx.x;  // 256
#pragma unroll
    for (int k = 0; k < 4; ++k) {
        int c = t + k * 256;
        float s = 0.f;
        for (int b = 0; b < 64; ++b) s += g_part[b * DIM + c];
        g_lmean[c] = s * (1.f / (float)LSZ);
    }
}

// q[j] = lmean . wq_row_j + bq[j]
__global__ void k_q(const float* __restrict__ wq, const float* __restrict__ bq) {
    int j = blockIdx.x, t = threadIdx.x;  // 1024 blocks x 256
    const float4* w  = (const float4*)(wq + (size_t)j * DIM);
    const float4* lm = (const float4*)g_lmean;
    float4 a = w[t], b = lm[t];
    float s = a.x*b.x + a.y*b.y + a.z*b.z + a.w*b.w;
    float tot = blockReduceSum(s);
    if (t == 0) g_q[j] = tot + bq[j];
}

// u[k] = sum_j wk[j][k] * q[j]  (partials then deterministic sum)
__global__ void k_upart(const float* __restrict__ wk) {
    int b = blockIdx.x, t = threadIdx.x;  // 64 blocks x 256
    float acc[4] = {0.f, 0.f, 0.f, 0.f};
    for (int jj = 0; jj < 16; ++jj) {
        int j = b * 16 + jj;
        float qj = g_q[j];
        const float* row = wk + (size_t)j * DIM;
#pragma unroll
        for (int k = 0; k < 4; ++k) acc[k] += row[t + k * 256] * qj;
    }
#pragma unroll
    for (int k = 0; k < 4; ++k) g_part[b * DIM + t + k * 256] = acc[k];
}
__global__ void k_usum() {
    int t = threadIdx.x;
#pragma unroll
    for (int k = 0; k < 4; ++k) {
        int c = t + k * 256;
        float s = 0.f;
        for (int b = 0; b < 64; ++b) s += g_part[b * DIM + c];
        g_u[c] = s;
    }
}

// attention logits (softmax monotone + uniform bk.q shift dropped -> argmax only)
__global__ void k_logits(const float* __restrict__ out_s) {
    int i = blockIdx.x, t = threadIdx.x;  // 512 blocks x 256
    const float4* s4 = (const float4*)(out_s + (size_t)i * DIM);
    const float4* u4 = (const float4*)g_u;
    float4 a = s4[t], b = u4[t];
    float s = a.x*b.x + a.y*b.y + a.z*b.z + a.w*b.w;
    float tot = blockReduceSum(s);
    if (t == 0) g_logits[i] = tot;
}

__global__ void k_pick(const float* __restrict__ out_s) {
    int t = threadIdx.x;  // 256
    float bv = -1e30f; int bi = 0;
    for (int i = t; i < SSZ; i += 256) {
        float v = g_logits[i];
        if (v > bv) { bv = v; bi = i; }
    }
    blockArgBest(bv, bi, 1, nullptr, &g_best_s);
    int bs = g_best_s;
    float loc = 0.f;
    const float4* src = (const float4*)(out_s + (size_t)bs * DIM);
    float4 v4 = src[t];
    ((float4*)g_cand)[t] = v4;
    loc = v4.x*v4.x + v4.y*v4.y + v4.z*v4.z + v4.w*v4.w;
    float tot = blockReduceSum(loc);
    if (t == 0) g_cnsq = tot;
}

// per-row dot(m_i, cand) and |m_i|^2
__global__ void k_mdots(const float* __restrict__ m) {
    int row = blockIdx.x, t = threadIdx.x;  // 4096 blocks x 256
    float4 mv = ((const float4*)(m + (size_t)row * DIM))[t];
    float4 cv = ((const float4*)g_cand)[t];
    float d = mv.x*cv.x + mv.y*cv.y + mv.z*cv.z + mv.w*cv.w;
    float n = mv.x*mv.x + mv.y*mv.y + mv.z*mv.z + mv.w*mv.w;
    float td = blockReduceSum(d);
    float tn = blockReduceSum(n);
    if (t == 0) { g_mdot[row] = td; g_mnsq[row] = tn; }
}

__global__ void k_mstats() {
    int t = threadIdx.x;  // 256
    float cinv = 1.f / fmaxf(sqrtf(g_cnsq), 1e-12f);
    float bv = -1e30f; int bi = 0;
    for (int i = t; i < MSZ; i += 256) {
        float inv = 1.f / fmaxf(sqrtf(g_mnsq[i]), 1e-12f);
        g_minv[i] = inv;
        float s = g_mdot[i] * inv * cinv;
        if (s > bv) { bv = s; bi = i; }
    }
    blockArgBest(bv, bi, 1, &g_simcand, &g_msi);
}

// max over strict lower triangle of cosine-sim matrix (the big GEMM)
#define TS 64
#define KT 16
__global__ __launch_bounds__(256) void k_pairmax(const float* __restrict__ M) {
    int b = blockIdx.x;
    int bi = (int)((sqrtf(8.f * b + 1.f) - 1.f) * 0.5f);
    while ((bi + 1) * (bi + 2) / 2 <= b) ++bi;
    while (bi * (bi + 1) / 2 > b) --bi;
    int bj = b - bi * (bi + 1) / 2;

    __shared__ float As[TS][KT + 1];
    __shared__ float Bs[TS][KT + 1];
    int tid = threadIdx.x;
    int tx = tid & 15, ty = tid >> 4;
    float acc[4][4];
#pragma unroll
    for (int i = 0; i < 4; ++i)
#pragma unroll
        for (int j = 0; j < 4; ++j) acc[i][j] = 0.f;

    int rowA = bi * TS, rowB = bj * TS;
    int lr = tid >> 2;            // 0..63
    int lc = (tid & 3) * 4;       // 0,4,8,12

    for (int k0 = 0; k0 < DIM; k0 += KT) {
        float4 a4 = *(const float4*)&M[(size_t)(rowA + lr) * DIM + k0 + lc];
        float4 b4 = *(const float4*)&M[(size_t)(rowB + lr) * DIM + k0 + lc];
        As[lr][lc] = a4.x; As[lr][lc+1] = a4.y; As[lr][lc+2] = a4.z; As[lr][lc+3] = a4.w;
        Bs[lr][lc] = b4.x; Bs[lr][lc+1] = b4.y; Bs[lr][lc+2] = b4.z; Bs[lr][lc+3] = b4.w;
        __syncthreads();
#pragma unroll
        for (int kk = 0; kk < KT; ++kk) {
            float a[4], bb[4];
#pragma unroll
            for (int i = 0; i < 4; ++i) a[i] = As[ty * 4 + i][kk];
#pragma unroll
            for (int j = 0; j < 4; ++j) bb[j] = Bs[tx * 4 + j][kk];
#pragma unroll
            for (int i = 0; i < 4; ++i)
#pragma unroll
                for (int j = 0; j < 4; ++j) acc[i][j] += a[i] * bb[j];
        }
        __syncthreads();
    }

    unsigned long long best = 0ULL;
#pragma unroll
    for (int i = 0; i < 4; ++i) {
        int gi = rowA + ty * 4 + i;
#pragma unroll
        for (int j = 0; j < 4; ++j) {
            int gj = rowB + tx * 4 + j;
            if (gi > gj) {
                float s = acc[i][j] * g_minv[gi] * g_minv[gj];
                unsigned flat = (unsigned)gi * MSZ + (unsigned)gj;
                unsigned long long key =
                    ((unsigned long long)ordf(s) << 32) | (0xFFFFFFFFu - flat);
                if (key > best) best = key;
            }
        }
    }
    __shared__ unsigned long long sred[256];
    sred[tid] = best;
    __syncthreads();
    for (int s = 128; s; s >>= 1) {
        if (tid < s && sred[tid + s] > sred[tid]) sred[tid] = sred[tid + s];
        __syncthreads();
    }
    if (tid == 0) atomicMax(&g_pairmax, sred[0]);
}

__global__ void k_utilstats(const float* __restrict__ mu, const float* __restrict__ lu) {
    int t = threadIdx.x;  // 256
    float s = 0.f, mv = 1e30f; int mi = 0; int z = 0;
    for (int i = t; i < MSZ; i += 256) {
        float v = mu[i];
        s += v;
        if (v == 0.f) z = 1;
        if (v < mv) { mv = v; mi = i; }
    }
    float tot = blockReduceSum(s);
    if (t == 0) g_mumean = tot / (float)MSZ;
    blockArgBest(mv, mi, 0, nullptr, &g_li);
    __shared__ int sz;
    if (t == 0) sz = 0;
    __syncthreads();
    if (z) atomicOr(&sz, 1);
    __syncthreads();
    if (t == 0) g_isfull = !sz;

    float s2 = 0.f, lv = 1e30f; int lji = 0;
    for (int i = t; i < LSZ; i += 256) {
        float v = lu[i];
        s2 += v;
        if (v < lv) { lv = v; lji = i; }
    }
    float t2 = blockReduceSum(s2);
    if (t == 0) g_lumean = t2 / (float)LSZ;
    blockArgBest(lv, lji, 0, nullptr, &g_lj);
}

__global__ void k_copy4(const float4* __restrict__ src, float4* __restrict__ dst, int n4) {
    int i = blockIdx.x * blockDim.x + threadIdx.x;
    int st = gridDim.x * blockDim.x;
    for (; i < n4; i += st) dst[i] = src[i];
}

__global__ void k_m_fixup(const float* __restrict__ m, const float* __restrict__ mu_in,
                          float* __restrict__ out_m, float* __restrict__ out_mu) {
    int t = threadIdx.x;  // 256
    for (int i = t; i < MSZ; i += 256) out_mu[i] = mu_in[i];
    __syncthreads();

    float mumean = g_mumean;
    int li = g_li, msi = g_msi;
    float simcand = g_simcand;
    unsigned long long pk = g_pairmax;
    float isim = iordf((unsigned)(pk >> 32));
    unsigned flat = 0xFFFFFFFFu - (unsigned)(pk & 0xFFFFFFFFu);
    int idx1 = flat / MSZ, idx2 = flat % MSZ;
    __shared__ float ssum;

    if (!g_isfull) {
        for (int c = t; c < DIM; c += 256) out_m[(size_t)li * DIM + c] = g_cand[c];
        if (t == 0) out_mu[li] = mumean + 1e-5f;
    } else if (simcand > 0.98f) {
        float loc = 0.f;
        for (int c = t; c < DIM; c += 256) {
            float v = (m[(size_t)msi * DIM + c] + g_cand[c]) * 0.5f;
            loc += v * v;
        }
        float tot = blockReduceSum(loc);
        if (t == 0) ssum = tot;
        __syncthreads();
        float inv = 1.f / fmaxf(sqrtf(ssum), 1e-12f);
        for (int c = t; c < DIM; c += 256) {
            float v = (m[(size_t)msi * DIM + c] + g_cand[c]) * 0.5f;
            out_m[(size_t)msi * DIM + c] = v * inv;
        }
        if (t == 0) out_mu[msi] = (mu_in[msi] + mumean) * 0.5f;
    } else if (isim > 0.98f) {
        float loc = 0.f;
        for (int c = t; c < DIM; c += 256) {
            float v = (m[(size_t)idx1 * DIM + c] + m[(size_t)idx2 * DIM + c]) * 0.5f;
            loc += v * v;
        }
        float tot = blockReduceSum(loc);
        if (t == 0) ssum = tot;
        __syncthreads();
        float inv = 1.f / fmaxf(sqrtf(ssum), 1e-12f);
        for (int c = t; c < DIM; c += 256) {
            float v = (m[(size_t)idx1 * DIM + c] + m[(size_t)idx2 * DIM + c]) * 0.5f;
            out_m[(size_t)idx1 * DIM + c] = v * inv;
            out_m[(size_t)idx2 * DIM + c] = g_cand[c];
        }
        if (t == 0) {
            float old1 = mu_in[idx1];
            float nu1 = (mu_in[idx1] + mu_in[idx2]) * 0.5f;
            out_mu[idx1] = nu1;
            float mean2 = mumean + (nu1 - old1) / (float)MSZ;  // mean recomputed after idx1 write
            out_mu[idx2] = mean2 + 1e-5f;
        }
    } else {
        if (g_cnsq > g_mnsq[li]) {  // norm compare == normsq compare (both >= 0)
            for (int c = t; c < DIM; c += 256) out_m[(size_t)li * DIM + c] = g_cand[c];
            if (t == 0) out_mu[li] = mumean + 1e-5f;
        }
    }
}

__global__ void k_mi(const float* __restrict__ out_mu) {
    int t = threadIdx.x;  // 256
    float bv = -1e30f; int bi = 0;
    for (int i = t; i < MSZ; i += 256) {
        float v = out_mu[i];
        if (v > bv) { bv = v; bi = i; }
    }
    blockArgBest(bv, bi, 1, nullptr, &g_mi);
}

__global__ void k_l_fixup(const float* __restrict__ l, const float* __restrict__ lu_in,
                          const float* __restrict__ out_m, float* __restrict__ out_l,
                          float* __restrict__ out_lu, float* __restrict__ out_tail,
                          const int* __restrict__ sptr) {
    int t = threadIdx.x;  // 256
    for (int i = t; i < LSZ; i += 256) out_lu[i] = lu_in[i];
    __syncthreads();
    int lj = g_lj, mi = g_mi;
    for (int c = t; c < DIM; c += 256)
        out_l[(size_t)lj * DIM + c] =
            0.9f * l[(size_t)lj * DIM + c] + 0.1f * out_m[(size_t)mi * DIM + c];
    if (t == 0) {
        out_lu[lj] = g_lumean;  // mean of pre-write values
        out_tail[0] = (float)(((*sptr) + KPROM) % SSZ);
    }
}

// ---------------- launch ----------------
extern "C" void kernel_launch(void* const* d_in, const int* in_sizes, int n_in,
                              void* d_out, int out_size) {
    const float* tok = (const float*)d_in[0];
    const float* s_in = (const float*)d_in[1];
    const float* m_in = (const float*)d_in[2];
    const float* l_in = (const float*)d_in[3];
    const float* mu_in = (const float*)d_in[4];
    const float* lu_in = (const float*)d_in[5];
    const float* wq = (const float*)d_in[6];
    const float* bq = (const float*)d_in[7];
    const float* wk = (const float*)d_in[8];
    // d_in[9] = bk: only shifts all logits uniformly -> argmax unchanged; unused
    const int* sptr = (const int*)d_in[10];

    float* out = (float*)d_out;
    float* out_s  = out;                       // 512*1024
    float* out_m  = out + 524288;              // 4096*1024
    float* out_l  = out + 4718592;             // 8192*1024
    float* out_mu = out + 13107200;            // 4096
    float* out_lu = out + 13111296;            // 8192
    float* out_p  = out + 13119488;            // 1

    k_init<<<1, 32>>>();
    k_rownorms<<<NCAND, 128>>>(tok);
    k_topk<<<1, 256>>>();
    k_build_s<<<SSZ, 256>>>(tok, s_in, sptr, out_s);

    k_lpart<<<64, 256>>>(l_in);
    k_lsum<<<1, 256>>>();
    k_q<<<DIM, 256>>>(wq, bq);
    k_upart<<<64, 256>>>(wk);
    k_usum<<<1, 256>>>();
    k_logits<<<SSZ, 256>>>(out_s);
    k_pick<<<1, 256>>>(out_s);

    k_mdots<<<MSZ, 256>>>(m_in);
    k_mstats<<<1, 256>>>();
    k_pairmax<<<(MSZ / TS) * (MSZ / TS + 1) / 2, 256>>>(m_in);

    k_utilstats<<<1, 256>>>(mu_in, lu_in);
    k_copy4<<<1024, 256>>>((const float4*)m_in, (float4*)out_m, MSZ * DIM / 4);
    k_m_fixup<<<1, 256>>>(m_in, mu_in, out_m, out_mu);
    k_mi<<<1, 256>>>(out_mu);
    k_copy4<<<2048, 256>>>((const float4*)l_in, (float4*)out_l, LSZ * DIM / 4);
    k_l_fixup<<<1, 256>>>(l_in, lu_in, out_m, out_l, out_lu, out_p, sptr);
}

// round 2
// speedup vs baseline: 1.0931x; 1.0931x over previous
#include <cuda_runtime.h>
#include <cuda_bf16.h>
#include <math.h>

#define DIM   1024
#define NCAND 16384
#define SSZ   512
#define MSZ   4096
#define LSZ   8192
#define KPROM 128

// ---------------- device scratch (no allocations allowed) ----------------
__device__ float g_norms[NCAND];
__device__ int   g_topidx[KPROM];
__device__ float g_part[64 * DIM];
__device__ float g_lmean[DIM];
__device__ float g_q[DIM];
__device__ float g_u[DIM];
__device__ float g_logits[SSZ];
__device__ int   g_best_s;
__device__ float g_cand[DIM];
__device__ float g_cnsq;
__device__ float g_mdot[MSZ];
__device__ float g_mnsq[MSZ];
__device__ float g_minv[MSZ];
__device__ int   g_msi;
__device__ float g_simcand;
__device__ unsigned long long g_pairmax;
__device__ float g_mumean, g_lumean;
__device__ int   g_li, g_lj, g_isfull, g_mi;
// bf16 fast path scratch
__device__ unsigned short g_mbf16[MSZ * DIM];   // 8 MB
__device__ float g_tmax64[64 * 64];             // per-64x64-tile bf16 sim max
__device__ unsigned g_bfmax;                    // global bf16 sim max (ordered float)

// ---------------- helpers ----------------
__device__ __forceinline__ float blockReduceSum(float v) {
    __shared__ float sh[32];
    int lane = threadIdx.x & 31, wid = threadIdx.x >> 5;
    __syncthreads();
#pragma unroll
    for (int o = 16; o; o >>= 1) v += __shfl_down_sync(0xFFFFFFFFu, v, o);
    if (lane == 0) sh[wid] = v;
    __syncthreads();
    int nw = (blockDim.x + 31) >> 5;
    v = (threadIdx.x < nw) ? sh[threadIdx.x] : 0.f;
    if (wid == 0) {
#pragma unroll
        for (int o = 16; o; o >>= 1) v += __shfl_down_sync(0xFFFFFFFFu, v, o);
    }
    return v;  // valid in tid 0
}

__device__ __forceinline__ void blockArgBest(float v, int idx, int maxMode,
                                             float* outv, int* outi) {
    __shared__ float sv[256];
    __shared__ int   si[256];
    __syncthreads();
    sv[threadIdx.x] = v; si[threadIdx.x] = idx;
    __syncthreads();
    for (int s = blockDim.x >> 1; s; s >>= 1) {
        if ((int)threadIdx.x < s) {
            float v2 = sv[threadIdx.x + s]; int i2 = si[threadIdx.x + s];
            bool better = maxMode
                ? (v2 > sv[threadIdx.x] || (v2 == sv[threadIdx.x] && i2 < si[threadIdx.x]))
                : (v2 < sv[threadIdx.x] || (v2 == sv[threadIdx.x] && i2 < si[threadIdx.x]));
            if (better) { sv[threadIdx.x] = v2; si[threadIdx.x] = i2; }
        }
        __syncthreads();
    }
    if (threadIdx.x == 0) { if (outv) *outv = sv[0]; *outi = si[0]; }
    __syncthreads();
}

__device__ __forceinline__ unsigned ordf(float f) {
    unsigned u = __float_as_uint(f);
    return (u & 0x80000000u) ? ~u : (u | 0x80000000u);
}
__device__ __forceinline__ float iordf(unsigned u) {
    unsigned b = (u & 0x80000000u) ? (u & 0x7FFFFFFFu) : ~u;
    return __uint_as_float(b);
}

__device__ __forceinline__ void mma16816(float* c, const unsigned* a, const unsigned* b) {
    asm volatile(
        "mma.sync.aligned.m16n8k16.row.col.f32.bf16.bf16.f32 "
        "{%0,%1,%2,%3}, {%4,%5,%6,%7}, {%8,%9}, {%0,%1,%2,%3};\n"
        : "+f"(c[0]), "+f"(c[1]), "+f"(c[2]), "+f"(c[3])
        : "r"(a[0]), "r"(a[1]), "r"(a[2]), "r"(a[3]), "r"(b[0]), "r"(b[1]));
}

// ---------------- kernels ----------------
__global__ void k_init() {
    if (threadIdx.x == 0) { g_pairmax = 0ULL; g_bfmax = 0u; }
}

__global__ void k_rownorms(const float* __restrict__ cand) {
    int row = blockIdx.x, t = threadIdx.x;  // 128 threads
    const float4* p = (const float4*)(cand + (size_t)row * DIM);
    float4 a = p[t], b = p[t + 128];
    float s = a.x*a.x + a.y*a.y + a.z*a.z + a.w*a.w
            + b.x*b.x + b.y*b.y + b.z*b.z + b.w*b.w;
    float tot = blockReduceSum(s);
    if (t == 0) g_norms[row] = tot;
}

__global__ void k_topk() {
    int tid = threadIdx.x;
    __shared__ float sv[256];
    __shared__ int   si[256];
    for (int it = 0; it < KPROM; ++it) {
        float bv = -1.f; int bi = 0;
        for (int i = tid; i < NCAND; i += 256) {
            float v = g_norms[i];
            if (v > bv) { bv = v; bi = i; }
        }
        sv[tid] = bv; si[tid] = bi;
        __syncthreads();
        for (int s = 128; s; s >>= 1) {
            if (tid < s) {
                if (sv[tid + s] > sv[tid] ||
                    (sv[tid + s] == sv[tid] && si[tid + s] < si[tid])) {
                    sv[tid] = sv[tid + s]; si[tid] = si[tid + s];
                }
            }
            __syncthreads();
        }
        if (tid == 0) { g_topidx[it] = si[0]; g_norms[si[0]] = -1.f; }
        __syncthreads();
    }
}

__global__ void k_build_s(const float* __restrict__ cand,
                          const float* __restrict__ s_in,
                          const int* __restrict__ sptr,
                          float* __restrict__ out_s) {
    int r = blockIdx.x, t = threadIdx.x;
    int sp = *sptr;
    int d = ((r - sp) % SSZ + SSZ) % SSZ;
    const float* src = (d < KPROM) ? (cand + (size_t)g_topidx[d] * DIM)
                                   : (s_in + (size_t)r * DIM);
    ((float4*)(out_s + (size_t)r * DIM))[t] = ((const float4*)src)[t];
}

__global__ void k_lpart(const float* __restrict__ l) {
    int b = blockIdx.x, t = threadIdx.x;
    float acc[4] = {0.f, 0.f, 0.f, 0.f};
    int r0 = b * 128;
    for (int r = 0; r < 128; ++r) {
        const float* row = l + (size_t)(r0 + r) * DIM;
#pragma unroll
        for (int k = 0; k < 4; ++k) acc[k] += row[t + k * 256];
    }
#pragma unroll
    for (int k = 0; k < 4; ++k) g_part[b * DIM + t + k * 256] = acc[k];
}
__global__ void k_lsum() {
    int t = threadIdx.x;
#pragma unroll
    for (int k = 0; k < 4; ++k) {
        int c = t + k * 256;
        float s = 0.f;
        for (int b = 0; b < 64; ++b) s += g_part[b * DIM + c];
        g_lmean[c] = s * (1.f / (float)LSZ);
    }
}

__global__ void k_q(const float* __restrict__ wq, const float* __restrict__ bq) {
    int j = blockIdx.x, t = threadIdx.x;
    const float4* w  = (const float4*)(wq + (size_t)j * DIM);
    const float4* lm = (const float4*)g_lmean;
    float4 a = w[t], b = lm[t];
    float s = a.x*b.x + a.y*b.y + a.z*b.z + a.w*b.w;
    float tot = blockReduceSum(s);
    if (t == 0) g_q[j] = tot + bq[j];
}

__global__ void k_upart(const float* __restrict__ wk) {
    int b = blockIdx.x, t = threadIdx.x;
    float acc[4] = {0.f, 0.f, 0.f, 0.f};
    for (int jj = 0; jj < 16; ++jj) {
        int j = b * 16 + jj;
        float qj = g_q[j];
        const float* row = wk + (size_t)j * DIM;
#pragma unroll
        for (int k = 0; k < 4; ++k) acc[k] += row[t + k * 256] * qj;
    }
#pragma unroll
    for (int k = 0; k < 4; ++k) g_part[b * DIM + t + k * 256] = acc[k];
}
__global__ void k_usum() {
    int t = threadIdx.x;
#pragma unroll
    for (int k = 0; k < 4; ++k) {
        int c = t + k * 256;
        float s = 0.f;
        for (int b = 0; b < 64; ++b) s += g_part[b * DIM + c];
        g_u[c] = s;
    }
}

__global__ void k_logits(const float* __restrict__ out_s) {
    int i = blockIdx.x, t = threadIdx.x;
    const float4* s4 = (const float4*)(out_s + (size_t)i * DIM);
    const float4* u4 = (const float4*)g_u;
    float4 a = s4[t], b = u4[t];
    float s = a.x*b.x + a.y*b.y + a.z*b.z + a.w*b.w;
    float tot = blockReduceSum(s);
    if (t == 0) g_logits[i] = tot;
}

__global__ void k_pick(const float* __restrict__ out_s) {
    int t = threadIdx.x;
    float bv = -1e30f; int bi = 0;
    for (int i = t; i < SSZ; i += 256) {
        float v = g_logits[i];
        if (v > bv) { bv = v; bi = i; }
    }
    blockArgBest(bv, bi, 1, nullptr, &g_best_s);
    int bs = g_best_s;
    const float4* src = (const float4*)(out_s + (size_t)bs * DIM);
    float4 v4 = src[t];
    ((float4*)g_cand)[t] = v4;
    float loc = v4.x*v4.x + v4.y*v4.y + v4.z*v4.z + v4.w*v4.w;
    float tot = blockReduceSum(loc);
    if (t == 0) g_cnsq = tot;
}

__global__ void k_mdots(const float* __restrict__ m) {
    int row = blockIdx.x, t = threadIdx.x;
    float4 mv = ((const float4*)(m + (size_t)row * DIM))[t];
    float4 cv = ((const float4*)g_cand)[t];
    float d = mv.x*cv.x + mv.y*cv.y + mv.z*cv.z + mv.w*cv.w;
    float n = mv.x*mv.x + mv.y*mv.y + mv.z*mv.z + mv.w*mv.w;
    float td = blockReduceSum(d);
    float tn = blockReduceSum(n);
    if (t == 0) { g_mdot[row] = td; g_mnsq[row] = tn; }
}

__global__ void k_mstats() {
    int t = threadIdx.x;
    float cinv = 1.f / fmaxf(sqrtf(g_cnsq), 1e-12f);
    float bv = -1e30f; int bi = 0;
    for (int i = t; i < MSZ; i += 256) {
        float inv = 1.f / fmaxf(sqrtf(g_mnsq[i]), 1e-12f);
        g_minv[i] = inv;
        float s = g_mdot[i] * inv * cinv;
        if (s > bv) { bv = s; bi = i; }
    }
    blockArgBest(bv, bi, 1, &g_simcand, &g_msi);
}

// fp32 -> bf16 conversion of m_memory
__device__ __forceinline__ unsigned short f2bf(float x) {
    __nv_bfloat16 h = __float2bfloat16_rn(x);
    return *(unsigned short*)&h;
}
__global__ void k_tobf16(const float* __restrict__ m) {
    int i = (blockIdx.x * blockDim.x + threadIdx.x) * 4;
    float4 v = *(const float4*)(m + i);
    ushort4 o;
    o.x = f2bf(v.x); o.y = f2bf(v.y); o.z = f2bf(v.z); o.w = f2bf(v.w);
    *(ushort4*)&g_mbf16[i] = o;
}

// ---- Pass 1: bf16 tensor-core sim GEMM over lower triangle, 128x128 tiles ----
#define LDB 40  // smem row stride in bf16 elems (80B): conflict-free frag loads
__global__ __launch_bounds__(256) void k_pairmax_bf16() {
    int b = blockIdx.x;  // 528 blocks over 32x32 triangular 128-tiles
    int bi = (int)((sqrtf(8.f * b + 1.f) - 1.f) * 0.5f);
    while ((bi + 1) * (bi + 2) / 2 <= b) ++bi;
    while (bi * (bi + 1) / 2 > b) --bi;
    int bj = b - bi * (bi + 1) / 2;
    int rowA = bi * 128, rowB = bj * 128;

    __shared__ __align__(16) unsigned short As[128 * LDB];
    __shared__ __align__(16) unsigned short Bs[128 * LDB];

    int tid = threadIdx.x, lane = tid & 31, warp = tid >> 5;
    int wm = warp >> 2, wn = warp & 3;           // 2 x 4 warp grid, warp tile 64x32
    int r = lane >> 2, q = lane & 3;

    float acc[4][4][4];
#pragma unroll
    for (int mi = 0; mi < 4; ++mi)
#pragma unroll
        for (int ni = 0; ni < 4; ++ni)
#pragma unroll
            for (int e = 0; e < 4; ++e) acc[mi][ni][e] = 0.f;

    int lr = tid >> 2;            // 0..63
    int lc = (tid & 3) * 8;       // 0,8,16,24 bf16 elems

    for (int k0 = 0; k0 < DIM; k0 += 32) {
        // load A/B tiles (128 x 32 bf16 each), 2 uint4 per thread per tile
        *(uint4*)&As[lr * LDB + lc] =
            *(const uint4*)&g_mbf16[(size_t)(rowA + lr) * DIM + k0 + lc];
        *(uint4*)&As[(lr + 64) * LDB + lc] =
            *(const uint4*)&g_mbf16[(size_t)(rowA + lr + 64) * DIM + k0 + lc];
        *(uint4*)&Bs[lr * LDB + lc] =
            *(const uint4*)&g_mbf16[(size_t)(rowB + lr) * DIM + k0 + lc];
        *(uint4*)&Bs[(lr + 64) * LDB + lc] =
            *(const uint4*)&g_mbf16[(size_t)(rowB + lr + 64) * DIM + k0 + lc];
        __syncthreads();

#pragma unroll
        for (int kk = 0; kk < 32; kk += 16) {
            unsigned bfr[4][2];
#pragma unroll
            for (int ni = 0; ni < 4; ++ni) {
                int rb = wn * 32 + ni * 8 + r;
                bfr[ni][0] = *(const unsigned*)&Bs[rb * LDB + kk + 2 * q];
                bfr[ni][1] = *(const unsigned*)&Bs[rb * LDB + kk + 2 * q + 8];
            }
#pragma unroll
            for (int mi = 0; mi < 4; ++mi) {
                int ra = wm * 64 + mi * 16 + r;
                unsigned af[4];
                af[0] = *(const unsigned*)&As[ra * LDB + kk + 2 * q];
                af[1] = *(const unsigned*)&As[(ra + 8) * LDB + kk + 2 * q];
                af[2] = *(const unsigned*)&As[ra * LDB + kk + 2 * q + 8];
                af[3] = *(const unsigned*)&As[(ra + 8) * LDB + kk + 2 * q + 8];
#pragma unroll
                for (int ni = 0; ni < 4; ++ni)
                    mma16816(acc[mi][ni], af, bfr[ni]);
            }
        }
        __syncthreads();
    }

    // epilogue: bf16 sims, warp max -> per-64x64-subtile max + global max
    float wmaxv = -1e30f;
#pragma unroll
    for (int mi = 0; mi < 4; ++mi) {
        int gi0 = rowA + wm * 64 + mi * 16 + r;
        float i0 = g_minv[gi0], i1 = g_minv[gi0 + 8];
#pragma unroll
        for (int ni = 0; ni < 4; ++ni) {
            int gj0 = rowB + wn * 32 + ni * 8 + 2 * q;
            float j0 = g_minv[gj0], j1 = g_minv[gj0 + 1];
            if (gi0 > gj0)     wmaxv = fmaxf(wmaxv, acc[mi][ni][0] * i0 * j0);
            if (gi0 > gj0 + 1) wmaxv = fmaxf(wmaxv, acc[mi][ni][1] * i0 * j1);
            if (gi0 + 8 > gj0)     wmaxv = fmaxf(wmaxv, acc[mi][ni][2] * i1 * j0);
            if (gi0 + 8 > gj0 + 1) wmaxv = fmaxf(wmaxv, acc[mi][ni][3] * i1 * j1);
        }
    }
#pragma unroll
    for (int o = 16; o; o >>= 1)
        wmaxv = fmaxf(wmaxv, __shfl_down_sync(0xFFFFFFFFu, wmaxv, o));
    __shared__ float wmax[8];
    if (lane == 0) wmax[warp] = wmaxv;
    __syncthreads();
    if (tid == 0) {
        float gmax = -1e30f;
        for (int sub = 0; sub < 4; ++sub) {
            int w0 = (sub >> 1) * 4 + (sub & 1) * 2;
            float m = fmaxf(wmax[w0], wmax[w0 + 1]);
            g_tmax64[(2 * bi + (sub >> 1)) * 64 + (2 * bj + (sub & 1))] = m;
            gmax = fmaxf(gmax, m);
        }
        atomicMax(&g_bfmax, ordf(gmax));
    }
}

// ---- Pass 2: exact fp32 recompute of qualifying 64x64 tiles only ----
#define TS 64
#define KT 16
__global__ __launch_bounds__(256) void k_pairmax_exact(const float* __restrict__ M) {
    int b = blockIdx.x;
    int bi = (int)((sqrtf(8.f * b + 1.f) - 1.f) * 0.5f);
    while ((bi + 1) * (bi + 2) / 2 <= b) ++bi;
    while (bi * (bi + 1) / 2 > b) --bi;
    int bj = b - bi * (bi + 1) / 2;

    // early-exit: bf16 error bound eps=0.0085 per sim; candidate tiles must have
    // bf16 tile max >= bf16 global max - 2*eps. (0.017 margin is rigorous.)
    float tmax = g_tmax64[bi * 64 + bj];
    float gmax = iordf(g_bfmax);
    if (tmax < gmax - 0.017f) return;

    __shared__ float As[TS][KT + 1];
    __shared__ float Bs[TS][KT + 1];
    int tid = threadIdx.x;
    int tx = tid & 15, ty = tid >> 4;
    float acc[4][4];
#pragma unroll
    for (int i = 0; i < 4; ++i)
#pragma unroll
        for (int j = 0; j < 4; ++j) acc[i][j] = 0.f;

    int rowA = bi * TS, rowB = bj * TS;
    int lr = tid >> 2;
    int lc = (tid & 3) * 4;

    for (int k0 = 0; k0 < DIM; k0 += KT) {
        float4 a4 = *(const float4*)&M[(size_t)(rowA + lr) * DIM + k0 + lc];
        float4 b4 = *(const float4*)&M[(size_t)(rowB + lr) * DIM + k0 + lc];
        As[lr][lc] = a4.x; As[lr][lc+1] = a4.y; As[lr][lc+2] = a4.z; As[lr][lc+3] = a4.w;
        Bs[lr][lc] = b4.x; Bs[lr][lc+1] = b4.y; Bs[lr][lc+2] = b4.z; Bs[lr][lc+3] = b4.w;
        __syncthreads();
#pragma unroll
        for (int kk = 0; kk < KT; ++kk) {
            float a[4], bb[4];
#pragma unroll
            for (int i = 0; i < 4; ++i) a[i] = As[ty * 4 + i][kk];
#pragma unroll
            for (int j = 0; j < 4; ++j) bb[j] = Bs[tx * 4 + j][kk];
#pragma unroll
            for (int i = 0; i < 4; ++i)
#pragma unroll
                for (int j = 0; j < 4; ++j) acc[i][j] += a[i] * bb[j];
        }
        __syncthreads();
    }

    unsigned long long best = 0ULL;
#pragma unroll
    for (int i = 0; i < 4; ++i) {
        int gi = rowA + ty * 4 + i;
#pragma unroll
        for (int j = 0; j < 4; ++j) {
            int gj = rowB + tx * 4 + j;
            if (gi > gj) {
                float s = acc[i][j] * g_minv[gi] * g_minv[gj];
                unsigned flat = (unsigned)gi * MSZ + (unsigned)gj;
                unsigned long long key =
                    ((unsigned long long)ordf(s) << 32) | (0xFFFFFFFFu - flat);
                if (key > best) best = key;
            }
        }
    }
    __shared__ unsigned long long sred[256];
    sred[tid] = best;
    __syncthreads();
    for (int s = 128; s; s >>= 1) {
        if (tid < s && sred[tid + s] > sred[tid]) sred[tid] = sred[tid + s];
        __syncthreads();
    }
    if (tid == 0) atomicMax(&g_pairmax, sred[0]);
}

__global__ void k_utilstats(const float* __restrict__ mu, const float* __restrict__ lu) {
    int t = threadIdx.x;
    float s = 0.f, mv = 1e30f; int mi = 0; int z = 0;
    for (int i = t; i < MSZ; i += 256) {
        float v = mu[i];
        s += v;
        if (v == 0.f) z = 1;
        if (v < mv) { mv = v; mi = i; }
    }
    float tot = blockReduceSum(s);
    if (t == 0) g_mumean = tot / (float)MSZ;
    blockArgBest(mv, mi, 0, nullptr, &g_li);
    __shared__ int sz;
    if (t == 0) sz = 0;
    __syncthreads();
    if (z) atomicOr(&sz, 1);
    __syncthreads();
    if (t == 0) g_isfull = !sz;

    float s2 = 0.f, lv = 1e30f; int lji = 0;
    for (int i = t; i < LSZ; i += 256) {
        float v = lu[i];
        s2 += v;
        if (v < lv) { lv = v; lji = i; }
    }
    float t2 = blockReduceSum(s2);
    if (t == 0) g_lumean = t2 / (float)LSZ;
    blockArgBest(lv, lji, 0, nullptr, &g_lj);
}

__global__ void k_copy4(const float4* __restrict__ src, float4* __restrict__ dst, int n4) {
    int i = blockIdx.x * blockDim.x + threadIdx.x;
    int st = gridDim.x * blockDim.x;
    for (; i < n4; i += st) dst[i] = src[i];
}

__global__ void k_m_fixup(const float* __restrict__ m, const float* __restrict__ mu_in,
                          float* __restrict__ out_m, float* __restrict__ out_mu) {
    int t = threadIdx.x;
    for (int i = t; i < MSZ; i += 256) out_mu[i] = mu_in[i];
    __syncthreads();

    float mumean = g_mumean;
    int li = g_li, msi = g_msi;
    float simcand = g_simcand;
    unsigned long long pk = g_pairmax;
    float isim = iordf((unsigned)(pk >> 32));
    unsigned flat = 0xFFFFFFFFu - (unsigned)(pk & 0xFFFFFFFFu);
    int idx1 = flat / MSZ, idx2 = flat % MSZ;
    __shared__ float ssum;

    if (!g_isfull) {
        for (int c = t; c < DIM; c += 256) out_m[(size_t)li * DIM + c] = g_cand[c];
        if (t == 0) out_mu[li] = mumean + 1e-5f;
    } else if (simcand > 0.98f) {
        float loc = 0.f;
        for (int c = t; c < DIM; c += 256) {
            float v = (m[(size_t)msi * DIM + c] + g_cand[c]) * 0.5f;
            loc += v * v;
        }
        float tot = blockReduceSum(loc);
        if (t == 0) ssum = tot;
        __syncthreads();
        float inv = 1.f / fmaxf(sqrtf(ssum), 1e-12f);
        for (int c = t; c < DIM; c += 256) {
            float v = (m[(size_t)msi * DIM + c] + g_cand[c]) * 0.5f;
            out_m[(size_t)msi * DIM + c] = v * inv;
        }
        if (t == 0) out_mu[msi] = (mu_in[msi] + mumean) * 0.5f;
    } else if (isim > 0.98f) {
        float loc = 0.f;
        for (int c = t; c < DIM; c += 256) {
            float v = (m[(size_t)idx1 * DIM + c] + m[(size_t)idx2 * DIM + c]) * 0.5f;
            loc += v * v;
        }
        float tot = blockReduceSum(loc);
        if (t == 0) ssum = tot;
        __syncthreads();
        float inv = 1.f / fmaxf(sqrtf(ssum), 1e-12f);
        for (int c = t; c < DIM; c += 256) {
            float v = (m[(size_t)idx1 * DIM + c] + m[(size_t)idx2 * DIM + c]) * 0.5f;
            out_m[(size_t)idx1 * DIM + c] = v * inv;
            out_m[(size_t)idx2 * DIM + c] = g_cand[c];
        }
        if (t == 0) {
            float old1 = mu_in[idx1];
            float nu1 = (mu_in[idx1] + mu_in[idx2]) * 0.5f;
            out_mu[idx1] = nu1;
            float mean2 = mumean + (nu1 - old1) / (float)MSZ;
            out_mu[idx2] = mean2 + 1e-5f;
        }
    } else {
        if (g_cnsq > g_mnsq[li]) {
            for (int c = t; c < DIM; c += 256) out_m[(size_t)li * DIM + c] = g_cand[c];
            if (t == 0) out_mu[li] = mumean + 1e-5f;
        }
    }
}

__global__ void k_mi(const float* __restrict__ out_mu) {
    int t = threadIdx.x;
    float bv = -1e30f; int bi = 0;
    for (int i = t; i < MSZ; i += 256) {
        float v = out_mu[i];
        if (v > bv) { bv = v; bi = i; }
    }
    blockArgBest(bv, bi, 1, nullptr, &g_mi);
}

__global__ void k_l_fixup(const float* __restrict__ l, const float* __restrict__ lu_in,
                          const float* __restrict__ out_m, float* __restrict__ out_l,
                          float* __restrict__ out_lu, float* __restrict__ out_tail,
                          const int* __restrict__ sptr) {
    int t = threadIdx.x;
    for (int i = t; i < LSZ; i += 256) out_lu[i] = lu_in[i];
    __syncthreads();
    int lj = g_lj, mi = g_mi;
    for (int c = t; c < DIM; c += 256)
        out_l[(size_t)lj * DIM + c] =
            0.9f * l[(size_t)lj * DIM + c] + 0.1f * out_m[(size_t)mi * DIM + c];
    if (t == 0) {
        out_lu[lj] = g_lumean;
        out_tail[0] = (float)(((*sptr) + KPROM) % SSZ);
    }
}

// ---------------- launch ----------------
extern "C" void kernel_launch(void* const* d_in, const int* in_sizes, int n_in,
                              void* d_out, int out_size) {
    const float* tok = (const float*)d_in[0];
    const float* s_in = (const float*)d_in[1];
    const float* m_in = (const float*)d_in[2];
    const float* l_in = (const float*)d_in[3];
    const float* mu_in = (const float*)d_in[4];
    const float* lu_in = (const float*)d_in[5];
    const float* wq = (const float*)d_in[6];
    const float* bq = (const float*)d_in[7];
    const float* wk = (const float*)d_in[8];
    const int* sptr = (const int*)d_in[10];

    float* out = (float*)d_out;
    float* out_s  = out;
    float* out_m  = out + 524288;
    float* out_l  = out + 4718592;
    float* out_mu = out + 13107200;
    float* out_lu = out + 13111296;
    float* out_p  = out + 13119488;

    k_init<<<1, 32>>>();
    k_rownorms<<<NCAND, 128>>>(tok);
    k_topk<<<1, 256>>>();
    k_build_s<<<SSZ, 256>>>(tok, s_in, sptr, out_s);

    k_lpart<<<64, 256>>>(l_in);
    k_lsum<<<1, 256>>>();
    k_q<<<DIM, 256>>>(wq, bq);
    k_upart<<<64, 256>>>(wk);
    k_usum<<<1, 256>>>();
    k_logits<<<SSZ, 256>>>(out_s);
    k_pick<<<1, 256>>>(out_s);

    k_mdots<<<MSZ, 256>>>(m_in);
    k_mstats<<<1, 256>>>();

    k_tobf16<<<MSZ * DIM / 1024, 256>>>(m_in);
    k_pairmax_bf16<<<32 * 33 / 2, 256>>>();
    k_pairmax_exact<<<(MSZ / TS) * (MSZ / TS + 1) / 2, 256>>>(m_in);

    k_utilstats<<<1, 256>>>(mu_in, lu_in);
    k_copy4<<<1024, 256>>>((const float4*)m_in, (float4*)out_m, MSZ * DIM / 4);
    k_m_fixup<<<1, 256>>>(m_in, mu_in, out_m, out_mu);
    k_mi<<<1, 256>>>(out_mu);
    k_copy4<<<2048, 256>>>((const float4*)l_in, (float4*)out_l, LSZ * DIM / 4);
    k_l_fixup<<<1, 256>>>(l_in, lu_in, out_m, out_l, out_lu, out_p, sptr);
}

// round 5
// speedup vs baseline: 1.8103x; 1.6561x over previous
#include <cuda_runtime.h>
#include <cuda_bf16.h>
#include <math.h>

#define DIM   1024
#define NCAND 16384
#define SSZ   512
#define MSZ   4096
#define LSZ   8192
#define KPROM 128

// ---------------- device scratch (no allocations allowed) ----------------
__device__ float g_norms[NCAND];
__device__ int   g_topidx[KPROM];
__device__ float g_part[64 * DIM];
__device__ float g_lmean[DIM];
__device__ float g_q[DIM];
__device__ float g_u[DIM];
__device__ float g_logits[SSZ];
__device__ int   g_best_s;
__device__ float g_cand[DIM];
__device__ float g_cnsq;
__device__ float g_mdot[MSZ];
__device__ float g_mnsq[MSZ];
__device__ float g_minv[MSZ];
__device__ int   g_msi;
__device__ float g_simcand;
__device__ unsigned long long g_pairmax;
__device__ float g_mumean, g_lumean;
__device__ int   g_li, g_lj, g_isfull, g_mi;
// int8 fast-path scratch
__device__ int   g_mi8[MSZ * 256];        // 4 MB: packed int8 rows (256 int32/row)
__device__ float g_sfac[MSZ];             // scale[row] * inv_norm[row] / 127-folded
__device__ float g_tmax64[64 * 64];       // per-64x64-tile int8 sim max
__device__ unsigned g_qmax;               // global int8 sim max (ordered float)

// ---------------- generic helpers ----------------
__device__ __forceinline__ float blockReduceSum(float v) {
    __shared__ float sh[32];
    int lane = threadIdx.x & 31, wid = threadIdx.x >> 5;
    __syncthreads();
#pragma unroll
    for (int o = 16; o; o >>= 1) v += __shfl_down_sync(0xFFFFFFFFu, v, o);
    if (lane == 0) sh[wid] = v;
    __syncthreads();
    int nw = (blockDim.x + 31) >> 5;
    v = (threadIdx.x < nw) ? sh[threadIdx.x] : 0.f;
    if (wid == 0) {
#pragma unroll
        for (int o = 16; o; o >>= 1) v += __shfl_down_sync(0xFFFFFFFFu, v, o);
    }
    return v;  // valid in tid 0
}

__device__ __forceinline__ float blockReduceMax(float v) {
    __shared__ float shm[32];
    int lane = threadIdx.x & 31, wid = threadIdx.x >> 5;
    __syncthreads();
#pragma unroll
    for (int o = 16; o; o >>= 1) v = fmaxf(v, __shfl_down_sync(0xFFFFFFFFu, v, o));
    if (lane == 0) shm[wid] = v;
    __syncthreads();
    int nw = (blockDim.x + 31) >> 5;
    v = (threadIdx.x < nw) ? shm[threadIdx.x] : -1e30f;
    if (wid == 0) {
#pragma unroll
        for (int o = 16; o; o >>= 1) v = fmaxf(v, __shfl_down_sync(0xFFFFFFFFu, v, o));
    }
    return v;  // valid in tid 0
}

__device__ __forceinline__ void blockArgBest(float v, int idx, int maxMode,
                                             float* outv, int* outi) {
    __shared__ float sv[256];
    __shared__ int   si[256];
    __syncthreads();
    sv[threadIdx.x] = v; si[threadIdx.x] = idx;
    __syncthreads();
    for (int s = blockDim.x >> 1; s; s >>= 1) {
        if ((int)threadIdx.x < s) {
            float v2 = sv[threadIdx.x + s]; int i2 = si[threadIdx.x + s];
            bool better = maxMode
                ? (v2 > sv[threadIdx.x] || (v2 == sv[threadIdx.x] && i2 < si[threadIdx.x]))
                : (v2 < sv[threadIdx.x] || (v2 == sv[threadIdx.x] && i2 < si[threadIdx.x]));
            if (better) { sv[threadIdx.x] = v2; si[threadIdx.x] = i2; }
        }
        __syncthreads();
    }
    if (threadIdx.x == 0) { if (outv) *outv = sv[0]; *outi = si[0]; }
    __syncthreads();
}

__device__ __forceinline__ unsigned ordf(float f) {
    unsigned u = __float_as_uint(f);
    return (u & 0x80000000u) ? ~u : (u | 0x80000000u);
}
__device__ __forceinline__ float iordf(unsigned u) {
    unsigned b = (u & 0x80000000u) ? (u & 0x7FFFFFFFu) : ~u;
    return __uint_as_float(b);
}

// ---------------- kernels ----------------
__global__ void k_init() {
    if (threadIdx.x == 0) { g_pairmax = 0ULL; g_qmax = 0u; }
}

// m_memory: row norms + int8 quantization (per-row scale), packed 4/int32
__global__ void k_mnq(const float* __restrict__ m) {
    int row = blockIdx.x, t = threadIdx.x;  // 4096 x 256
    float4 v = ((const float4*)(m + (size_t)row * DIM))[t];
    float nsq = v.x*v.x + v.y*v.y + v.z*v.z + v.w*v.w;
    float mab = fmaxf(fmaxf(fabsf(v.x), fabsf(v.y)), fmaxf(fabsf(v.z), fabsf(v.w)));
    float tn = blockReduceSum(nsq);
    float tm = blockReduceMax(mab);
    __shared__ float s_is;
    if (t == 0) {
        g_mnsq[row] = tn;
        float inv = 1.f / fmaxf(sqrtf(tn), 1e-12f);
        g_minv[row] = inv;
        float scale = (tm > 0.f) ? tm / 127.f : 1.f;
        g_sfac[row] = scale * inv;                 // sim = acc * sfacA * sfacB
        s_is = (tm > 0.f) ? 127.f / tm : 0.f;
    }
    __syncthreads();
    float is = s_is;
    int q0 = max(-127, min(127, __float2int_rn(v.x * is)));
    int q1 = max(-127, min(127, __float2int_rn(v.y * is)));
    int q2 = max(-127, min(127, __float2int_rn(v.z * is)));
    int q3 = max(-127, min(127, __float2int_rn(v.w * is)));
    g_mi8[row * 256 + t] = (q0 & 0xFF) | ((q1 & 0xFF) << 8) |
                           ((q2 & 0xFF) << 16) | ((q3 & 0xFF) << 24);
}

__global__ void k_rownorms(const float* __restrict__ cand) {
    int row = blockIdx.x, t = threadIdx.x;  // 16384 x 128
    const float4* p = (const float4*)(cand + (size_t)row * DIM);
    float4 a = p[t], b = p[t + 128];
    float s = a.x*a.x + a.y*a.y + a.z*a.z + a.w*a.w
            + b.x*b.x + b.y*b.y + b.z*b.z + b.w*b.w;
    float tot = blockReduceSum(s);
    if (t == 0) g_norms[row] = tot;
}

__global__ void k_lpart(const float* __restrict__ l) {
    int b = blockIdx.x, t = threadIdx.x;  // 64 x 256
    float acc[4] = {0.f, 0.f, 0.f, 0.f};
    int r0 = b * 128;
    for (int r = 0; r < 128; ++r) {
        const float* row = l + (size_t)(r0 + r) * DIM;
#pragma unroll
        for (int k = 0; k < 4; ++k) acc[k] += row[t + k * 256];
    }
#pragma unroll
    for (int k = 0; k < 4; ++k) g_part[b * DIM + t + k * 256] = acc[k];
}

// ---- fast top-128: register-resident unique keys, cached local max ----
__global__ __launch_bounds__(1024) void k_topk() {
    int tid = threadIdx.x, lane = tid & 31, warp = tid >> 5;
    unsigned long long key[16];
#pragma unroll
    for (int i = 0; i < 16; ++i) {
        int idx = tid + i * 1024;
        key[i] = ((unsigned long long)ordf(g_norms[idx]) << 32) |
                 (unsigned long long)(0xFFFFFFFFu - (unsigned)idx);
    }
    unsigned long long lmax = 0ULL;
#pragma unroll
    for (int i = 0; i < 16; ++i) if (key[i] > lmax) lmax = key[i];

    __shared__ unsigned long long wkey[32];
    __shared__ unsigned long long winner;
    for (int it = 0; it < KPROM; ++it) {
        unsigned long long k = lmax;
#pragma unroll
        for (int o = 16; o; o >>= 1) {
            unsigned long long o2 = __shfl_down_sync(0xFFFFFFFFu, k, o);
            if (o2 > k) k = o2;
        }
        if (lane == 0) wkey[warp] = k;
        __syncthreads();
        if (warp == 0) {
            unsigned long long k2 = wkey[lane];
#pragma unroll
            for (int o = 16; o; o >>= 1) {
                unsigned long long o2 = __shfl_down_sync(0xFFFFFFFFu, k2, o);
                if (o2 > k2) k2 = o2;
            }
            if (lane == 0) {
                winner = k2;
                g_topidx[it] = (int)(0xFFFFFFFFu - (unsigned)(k2 & 0xFFFFFFFFu));
            }
        }
        __syncthreads();
        unsigned long long w = winner;
        if (lmax == w) {                      // keys unique: exactly one owner
            unsigned long long nm = 0ULL;
#pragma unroll
            for (int i = 0; i < 16; ++i) {
                if (key[i] == w) key[i] = 0ULL;
                if (key[i] > nm) nm = key[i];
            }
            lmax = nm;
        }
    }
}

// ---- Pass 1: int8 DP4A pair-similarity, 128x128 lower-tri tiles ----
// smem tiles stored K-transposed [kk][row], stride 132 ints (16B aligned rows)
__global__ __launch_bounds__(256) void k_pairmax_i8() {
    __shared__ int As[32 * 132];
    __shared__ int Bs[32 * 132];
    __shared__ float sfA[128], sfB[128];
    __shared__ float wsub[8][4];

    int b = blockIdx.x;  // 528 blocks, 32x32 triangle incl diagonal
    int bi = (int)((sqrtf(8.f * b + 1.f) - 1.f) * 0.5f);
    while ((bi + 1) * (bi + 2) / 2 <= b) ++bi;
    while (bi * (bi + 1) / 2 > b) --bi;
    int bj = b - bi * (bi + 1) / 2;
    int rowA = bi * 128, rowB = bj * 128;

    int tid = threadIdx.x, lane = tid & 31, warp = tid >> 5;
    int tx = tid & 15, ty = tid >> 4;

    if (tid < 128) sfA[tid] = g_sfac[rowA + tid];
    else           sfB[tid - 128] = g_sfac[rowB + tid - 128];

    int acc[8][8];
#pragma unroll
    for (int i = 0; i < 8; ++i)
#pragma unroll
        for (int j = 0; j < 8; ++j) acc[i][j] = 0;

    for (int c = 0; c < 8; ++c) {           // K chunks of 128 int8 (32 int32)
        __syncthreads();
#pragma unroll
        for (int v = 0; v < 4; ++v) {       // 16 ints per thread per matrix
            int n = v * 1024 + tid * 4;
            int row = n >> 5, kk = n & 31;
            int4 a4 = *(const int4*)&g_mi8[(size_t)(rowA + row) * 256 + c * 32 + kk];
            As[(kk + 0) * 132 + row] = a4.x;
            As[(kk + 1) * 132 + row] = a4.y;
            As[(kk + 2) * 132 + row] = a4.z;
            As[(kk + 3) * 132 + row] = a4.w;
            int4 b4 = *(const int4*)&g_mi8[(size_t)(rowB + row) * 256 + c * 32 + kk];
            Bs[(kk + 0) * 132 + row] = b4.x;
            Bs[(kk + 1) * 132 + row] = b4.y;
            Bs[(kk + 2) * 132 + row] = b4.z;
            Bs[(kk + 3) * 132 + row] = b4.w;
        }
        __syncthreads();
#pragma unroll 4
        for (int kk = 0; kk < 32; ++kk) {
            int4 al = *(const int4*)&As[kk * 132 + ty * 8];
            int4 ah = *(const int4*)&As[kk * 132 + ty * 8 + 4];
            int4 bl = *(const int4*)&Bs[kk * 132 + tx * 8];
            int4 bh = *(const int4*)&Bs[kk * 132 + tx * 8 + 4];
            int a[8] = {al.x, al.y, al.z, al.w, ah.x, ah.y, ah.z, ah.w};
            int bb[8] = {bl.x, bl.y, bl.z, bl.w, bh.x, bh.y, bh.z, bh.w};
#pragma unroll
            for (int i = 0; i < 8; ++i)
#pragma unroll
                for (int j = 0; j < 8; ++j)
                    acc[i][j] = __dp4a(a[i], bb[j], acc[i][j]);
        }
    }

    // epilogue: per-thread subtile max of int8 sims (thread maps to one 64x64 sub)
    float mx = -1e30f;
#pragma unroll
    for (int i = 0; i < 8; ++i) {
        int gi = rowA + ty * 8 + i;
        float fi = sfA[ty * 8 + i];
#pragma unroll
        for (int j = 0; j < 8; ++j) {
            int gj = rowB + tx * 8 + j;
            if (gi > gj) mx = fmaxf(mx, (float)acc[i][j] * fi * sfB[tx * 8 + j]);
        }
    }
    // lane = (ty&1)*16 + tx; reduce within 8-lane groups (fixed tx>>3 half)
#pragma unroll
    for (int o = 4; o; o >>= 1) mx = fmaxf(mx, __shfl_xor_sync(0xFFFFFFFFu, mx, o));
    if ((lane & 7) == 0) wsub[warp][lane >> 3] = mx;  // slot = (ty&1)*2 + ch
    __syncthreads();
    if (tid == 0) {
        float g = -1e30f;
        for (int rh = 0; rh < 2; ++rh)
            for (int ch = 0; ch < 2; ++ch) {
                float m = -1e30f;
                for (int w = rh * 4; w < rh * 4 + 4; ++w)
                    m = fmaxf(m, fmaxf(wsub[w][ch], wsub[w][ch + 2]));
                g_tmax64[(2 * bi + rh) * 64 + (2 * bj + ch)] = m;
                g = fmaxf(g, m);
            }
        atomicMax(&g_qmax, ordf(g));
    }
}

__global__ void k_build_s(const float* __restrict__ cand,
                          const float* __restrict__ s_in,
                          const int* __restrict__ sptr,
                          float* __restrict__ out_s) {
    int r = blockIdx.x, t = threadIdx.x;
    int sp = *sptr;
    int d = ((r - sp) % SSZ + SSZ) % SSZ;
    const float* src = (d < KPROM) ? (cand + (size_t)g_topidx[d] * DIM)
                                   : (s_in + (size_t)r * DIM);
    ((float4*)(out_s + (size_t)r * DIM))[t] = ((const float4*)src)[t];
}

__global__ void k_lsum() {
    int t = threadIdx.x;
#pragma unroll
    for (int k = 0; k < 4; ++k) {
        int c = t + k * 256;
        float s = 0.f;
        for (int b = 0; b < 64; ++b) s += g_part[b * DIM + c];
        g_lmean[c] = s * (1.f / (float)LSZ);
    }
}

__global__ void k_q(const float* __restrict__ wq, const float* __restrict__ bq) {
    int j = blockIdx.x, t = threadIdx.x;
    const float4* w  = (const float4*)(wq + (size_t)j * DIM);
    const float4* lm = (const float4*)g_lmean;
    float4 a = w[t], b = lm[t];
    float s = a.x*b.x + a.y*b.y + a.z*b.z + a.w*b.w;
    float tot = blockReduceSum(s);
    if (t == 0) g_q[j] = tot + bq[j];
}

__global__ void k_upart(const float* __restrict__ wk) {
    int b = blockIdx.x, t = threadIdx.x;
    float acc[4] = {0.f, 0.f, 0.f, 0.f};
    for (int jj = 0; jj < 16; ++jj) {
        int j = b * 16 + jj;
        float qj = g_q[j];
        const float* row = wk + (size_t)j * DIM;
#pragma unroll
        for (int k = 0; k < 4; ++k) acc[k] += row[t + k * 256] * qj;
    }
#pragma unroll
    for (int k = 0; k < 4; ++k) g_part[b * DIM + t + k * 256] = acc[k];
}
__global__ void k_usum() {
    int t = threadIdx.x;
#pragma unroll
    for (int k = 0; k < 4; ++k) {
        int c = t + k * 256;
        float s = 0.f;
        for (int b = 0; b < 64; ++b) s += g_part[b * DIM + c];
        g_u[c] = s;
    }
}

__global__ void k_logits(const float* __restrict__ out_s) {
    int i = blockIdx.x, t = threadIdx.x;
    const float4* s4 = (const float4*)(out_s + (size_t)i * DIM);
    const float4* u4 = (const float4*)g_u;
    float4 a = s4[t], b = u4[t];
    float s = a.x*b.x + a.y*b.y + a.z*b.z + a.w*b.w;
    float tot = blockReduceSum(s);
    if (t == 0) g_logits[i] = tot;
}

__global__ void k_pick(const float* __restrict__ out_s) {
    int t = threadIdx.x;
    float bv = -1e30f; int bi = 0;
    for (int i = t; i < SSZ; i += 256) {
        float v = g_logits[i];
        if (v > bv) { bv = v; bi = i; }
    }
    blockArgBest(bv, bi, 1, nullptr, &g_best_s);
    int bs = g_best_s;
    const float4* src = (const float4*)(out_s + (size_t)bs * DIM);
    float4 v4 = src[t];
    ((float4*)g_cand)[t] = v4;
    float loc = v4.x*v4.x + v4.y*v4.y + v4.z*v4.z + v4.w*v4.w;
    float tot = blockReduceSum(loc);
    if (t == 0) g_cnsq = tot;
}

__global__ void k_mdots(const float* __restrict__ m) {
    int row = blockIdx.x, t = threadIdx.x;
    float4 mv = ((const float4*)(m + (size_t)row * DIM))[t];
    float4 cv = ((const float4*)g_cand)[t];
    float d = mv.x*cv.x + mv.y*cv.y + mv.z*cv.z + mv.w*cv.w;
    float td = blockReduceSum(d);
    if (t == 0) g_mdot[row] = td;
}

__global__ void k_mstats() {
    int t = threadIdx.x;
    float cinv = 1.f / fmaxf(sqrtf(g_cnsq), 1e-12f);
    float bv = -1e30f; int bi = 0;
    for (int i = t; i < MSZ; i += 256) {
        float s = g_mdot[i] * g_minv[i] * cinv;
        if (s > bv) { bv = s; bi = i; }
    }
    blockArgBest(bv, bi, 1, &g_simcand, &g_msi);
}

// ---- Pass 2: exact fp32 recompute of tiles that can hold the true max ----
#define TS 64
#define KT 16
__global__ __launch_bounds__(256) void k_pairmax_exact(const float* __restrict__ M) {
    int b = blockIdx.x;
    int bi = (int)((sqrtf(8.f * b + 1.f) - 1.f) * 0.5f);
    while ((bi + 1) * (bi + 2) / 2 <= b) ++bi;
    while (bi * (bi + 1) / 2 > b) --bi;
    int bj = b - bi * (bi + 1) / 2;

    // int8 per-pair sim error <= 0.011 (Hoeffding, p_fail ~1e-30); margin 0.025
    float tmax = g_tmax64[bi * 64 + bj];
    float gmax = iordf(g_qmax);
    if (tmax < gmax - 0.025f) return;

    __shared__ float As[TS][KT + 1];
    __shared__ float Bs[TS][KT + 1];
    int tid = threadIdx.x;
    int tx = tid & 15, ty = tid >> 4;
    float acc[4][4];
#pragma unroll
    for (int i = 0; i < 4; ++i)
#pragma unroll
        for (int j = 0; j < 4; ++j) acc[i][j] = 0.f;

    int rowA = bi * TS, rowB = bj * TS;
    int lr = tid >> 2;
    int lc = (tid & 3) * 4;

    for (int k0 = 0; k0 < DIM; k0 += KT) {
        float4 a4 = *(const float4*)&M[(size_t)(rowA + lr) * DIM + k0 + lc];
        float4 b4 = *(const float4*)&M[(size_t)(rowB + lr) * DIM + k0 + lc];
        As[lr][lc] = a4.x; As[lr][lc+1] = a4.y; As[lr][lc+2] = a4.z; As[lr][lc+3] = a4.w;
        Bs[lr][lc] = b4.x; Bs[lr][lc+1] = b4.y; Bs[lr][lc+2] = b4.z; Bs[lr][lc+3] = b4.w;
        __syncthreads();
#pragma unroll
        for (int kk = 0; kk < KT; ++kk) {
            float a[4], bb[4];
#pragma unroll
            for (int i = 0; i < 4; ++i) a[i] = As[ty * 4 + i][kk];
#pragma unroll
            for (int j = 0; j < 4; ++j) bb[j] = Bs[tx * 4 + j][kk];
#pragma unroll
            for (int i = 0; i < 4; ++i)
#pragma unroll
                for (int j = 0; j < 4; ++j) acc[i][j] += a[i] * bb[j];
        }
        __syncthreads();
    }

    unsigned long long best = 0ULL;
#pragma unroll
    for (int i = 0; i < 4; ++i) {
        int gi = rowA + ty * 4 + i;
#pragma unroll
        for (int j = 0; j < 4; ++j) {
            int gj = rowB + tx * 4 + j;
            if (gi > gj) {
                float s = acc[i][j] * g_minv[gi] * g_minv[gj];
                unsigned flat = (unsigned)gi * MSZ + (unsigned)gj;
                unsigned long long key =
                    ((unsigned long long)ordf(s) << 32) | (0xFFFFFFFFu - flat);
                if (key > best) best = key;
            }
        }
    }
    __shared__ unsigned long long sred[256];
    sred[tid] = best;
    __syncthreads();
    for (int s = 128; s; s >>= 1) {
        if (tid < s && sred[tid + s] > sred[tid]) sred[tid] = sred[tid + s];
        __syncthreads();
    }
    if (tid == 0) atomicMax(&g_pairmax, sred[0]);
}

__global__ void k_utilstats(const float* __restrict__ mu, const float* __restrict__ lu) {
    int t = threadIdx.x;
    float s = 0.f, mv = 1e30f; int mi = 0; int z = 0;
    for (int i = t; i < MSZ; i += 256) {
        float v = mu[i];
        s += v;
        if (v == 0.f) z = 1;
        if (v < mv) { mv = v; mi = i; }
    }
    float tot = blockReduceSum(s);
    if (t == 0) g_mumean = tot / (float)MSZ;
    blockArgBest(mv, mi, 0, nullptr, &g_li);
    __shared__ int sz;
    if (t == 0) sz = 0;
    __syncthreads();
    if (z) atomicOr(&sz, 1);
    __syncthreads();
    if (t == 0) g_isfull = !sz;

    float s2 = 0.f, lv = 1e30f; int lji = 0;
    for (int i = t; i < LSZ; i += 256) {
        float v = lu[i];
        s2 += v;
        if (v < lv) { lv = v; lji = i; }
    }
    float t2 = blockReduceSum(s2);
    if (t == 0) g_lumean = t2 / (float)LSZ;
    blockArgBest(lv, lji, 0, nullptr, &g_lj);
}

__global__ void k_copy4(const float4* __restrict__ src, float4* __restrict__ dst, int n4) {
    int i = blockIdx.x * blockDim.x + threadIdx.x;
    int st = gridDim.x * blockDim.x;
    for (; i < n4; i += st) dst[i] = src[i];
}

__global__ void k_m_fixup(const float* __restrict__ m, const float* __restrict__ mu_in,
                          float* __restrict__ out_m, float* __restrict__ out_mu) {
    int t = threadIdx.x;
    for (int i = t; i < MSZ; i += 256) out_mu[i] = mu_in[i];
    __syncthreads();

    float mumean = g_mumean;
    int li = g_li, msi = g_msi;
    float simcand = g_simcand;
    unsigned long long pk = g_pairmax;
    float isim = iordf((unsigned)(pk >> 32));
    unsigned flat = 0xFFFFFFFFu - (unsigned)(pk & 0xFFFFFFFFu);
    int idx1 = flat / MSZ, idx2 = flat % MSZ;
    __shared__ float ssum;

    if (!g_isfull) {
        for (int c = t; c < DIM; c += 256) out_m[(size_t)li * DIM + c] = g_cand[c];
        if (t == 0) out_mu[li] = mumean + 1e-5f;
    } else if (simcand > 0.98f) {
        float loc = 0.f;
        for (int c = t; c < DIM; c += 256) {
            float v = (m[(size_t)msi * DIM + c] + g_cand[c]) * 0.5f;
            loc += v * v;
        }
        float tot = blockReduceSum(loc);
        if (t == 0) ssum = tot;
        __syncthreads();
        float inv = 1.f / fmaxf(sqrtf(ssum), 1e-12f);
        for (int c = t; c < DIM; c += 256) {
            float v = (m[(size_t)msi * DIM + c] + g_cand[c]) * 0.5f;
            out_m[(size_t)msi * DIM + c] = v * inv;
        }
        if (t == 0) out_mu[msi] = (mu_in[msi] + mumean) * 0.5f;
    } else if (isim > 0.98f) {
        float loc = 0.f;
        for (int c = t; c < DIM; c += 256) {
            float v = (m[(size_t)idx1 * DIM + c] + m[(size_t)idx2 * DIM + c]) * 0.5f;
            loc += v * v;
        }
        float tot = blockReduceSum(loc);
        if (t == 0) ssum = tot;
        __syncthreads();
        float inv = 1.f / fmaxf(sqrtf(ssum), 1e-12f);
        for (int c = t; c < DIM; c += 256) {
            float v = (m[(size_t)idx1 * DIM + c] + m[(size_t)idx2 * DIM + c]) * 0.5f;
            out_m[(size_t)idx1 * DIM + c] = v * inv;
            out_m[(size_t)idx2 * DIM + c] = g_cand[c];
        }
        if (t == 0) {
            float old1 = mu_in[idx1];
            float nu1 = (mu_in[idx1] + mu_in[idx2]) * 0.5f;
            out_mu[idx1] = nu1;
            float mean2 = mumean + (nu1 - old1) / (float)MSZ;
            out_mu[idx2] = mean2 + 1e-5f;
        }
    } else {
        if (g_cnsq > g_mnsq[li]) {
            for (int c = t; c < DIM; c += 256) out_m[(size_t)li * DIM + c] = g_cand[c];
            if (t == 0) out_mu[li] = mumean + 1e-5f;
        }
    }
}

__global__ void k_mi(const float* __restrict__ out_mu) {
    int t = threadIdx.x;
    float bv = -1e30f; int bi = 0;
    for (int i = t; i < MSZ; i += 256) {
        float v = out_mu[i];
        if (v > bv) { bv = v; bi = i; }
    }
    blockArgBest(bv, bi, 1, nullptr, &g_mi);
}

__global__ void k_l_fixup(const float* __restrict__ l, const float* __restrict__ lu_in,
                          const float* __restrict__ out_m, float* __restrict__ out_l,
                          float* __restrict__ out_lu, float* __restrict__ out_tail,
                          const int* __restrict__ sptr) {
    int t = threadIdx.x;
    for (int i = t; i < LSZ; i += 256) out_lu[i] = lu_in[i];
    __syncthreads();
    int lj = g_lj, mi = g_mi;
    for (int c = t; c < DIM; c += 256)
        out_l[(size_t)lj * DIM + c] =
            0.9f * l[(size_t)lj * DIM + c] + 0.1f * out_m[(size_t)mi * DIM + c];
    if (t == 0) {
        out_lu[lj] = g_lumean;
        out_tail[0] = (float)(((*sptr) + KPROM) % SSZ);
    }
}

// ---------------- launch ----------------
extern "C" void kernel_launch(void* const* d_in, const int* in_sizes, int n_in,
                              void* d_out, int out_size) {
    const float* tok = (const float*)d_in[0];
    const float* s_in = (const float*)d_in[1];
    const float* m_in = (const float*)d_in[2];
    const float* l_in = (const float*)d_in[3];
    const float* mu_in = (const float*)d_in[4];
    const float* lu_in = (const float*)d_in[5];
    const float* wq = (const float*)d_in[6];
    const float* bq = (const float*)d_in[7];
    const float* wk = (const float*)d_in[8];
    const int* sptr = (const int*)d_in[10];

    float* out = (float*)d_out;
    float* out_s  = out;
    float* out_m  = out + 524288;
    float* out_l  = out + 4718592;
    float* out_mu = out + 13107200;
    float* out_lu = out + 13111296;
    float* out_p  = out + 13119488;

    // launches 1-5, then the dp4a GEMM as launch #6 (ncu -s 5 -c 1 captures it)
    k_init<<<1, 32>>>();
    k_mnq<<<MSZ, 256>>>(m_in);
    k_rownorms<<<NCAND, 128>>>(tok);
    k_lpart<<<64, 256>>>(l_in);
    k_topk<<<1, 1024>>>();
    k_pairmax_i8<<<32 * 33 / 2, 256>>>();

    k_build_s<<<SSZ, 256>>>(tok, s_in, sptr, out_s);
    k_lsum<<<1, 256>>>();
    k_q<<<DIM, 256>>>(wq, bq);
    k_upart<<<64, 256>>>(wk);
    k_usum<<<1, 256>>>();
    k_logits<<<SSZ, 256>>>(out_s);
    k_pick<<<1, 256>>>(out_s);
    k_mdots<<<MSZ, 256>>>(m_in);
    k_mstats<<<1, 256>>>();
    k_pairmax_exact<<<(MSZ / TS) * (MSZ / TS + 1) / 2, 256>>>(m_in);

    k_utilstats<<<1, 256>>>(mu_in, lu_in);
    k_copy4<<<1024, 256>>>((const float4*)m_in, (float4*)out_m, MSZ * DIM / 4);
    k_m_fixup<<<1, 256>>>(m_in, mu_in, out_m, out_mu);
    k_mi<<<1, 256>>>(out_mu);
    k_copy4<<<2048, 256>>>((const float4*)l_in, (float4*)out_l, LSZ * DIM / 4);
    k_l_fixup<<<1, 256>>>(l_in, lu_in, out_m, out_l, out_lu, out_p, sptr);
}